// round 15
// baseline (speedup 1.0000x reference)
#include <cuda_runtime.h>
#include <cuda_bf16.h>
#include <mma.h>
#include <cstdint>
#include <math.h>

using namespace nvcuda;

#define NUM_C   10
#define OUT_CH  16
#define BATCH   256
#define KDIM    9216
#define K4      (KDIM / 4)
#define NCOL    160

#define KSPLIT  72
#define KPER    128
#define KT      16
#define NSTG    8
#define NTHR    128
#define LDA     24
#define PSTRIDE (KSPLIT * NCOL)   /* 11520 */

/* partials: [b(256)][ks(72)][n(160)] — per-b contiguous for routing */
__device__ float g_Upart[BATCH * KSPLIT * NCOL];
/* W in NATIVE layout [c][k][o], bf16 hi/lo */
__device__ __nv_bfloat16 g_Wh[NUM_C * KDIM * OUT_CH];
__device__ __nv_bfloat16 g_Wl[NUM_C * KDIM * OUT_CH];

__device__ __forceinline__ uint32_t smem_u32(const void* p) {
    uint32_t a;
    asm("{ .reg .u64 t; cvta.to.shared.u64 t, %1; cvt.u32.u64 %0, t; }"
        : "=r"(a) : "l"(p));
    return a;
}
__device__ __forceinline__ void cp16(uint32_t dst, const void* src) {
    asm volatile("cp.async.cg.shared.global [%0], [%1], 16;"
                 :: "r"(dst), "l"(src) : "memory");
}
__device__ __forceinline__ void cp_commit() {
    asm volatile("cp.async.commit_group;" ::: "memory");
}
__device__ __forceinline__ void cp_wait1() {
    asm volatile("cp.async.wait_group 1;" ::: "memory");
}
__device__ __forceinline__ void cp_wait0() {
    asm volatile("cp.async.wait_group 0;" ::: "memory");
}
__device__ __forceinline__ void cvt_split2(float a, float b,
                                           uint32_t& hi2, uint32_t& lo2) {
    asm("cvt.rn.bf16x2.f32 %0, %1, %2;" : "=r"(hi2) : "f"(b), "f"(a));
    float fa = __uint_as_float(hi2 << 16);
    float fb = __uint_as_float(hi2 & 0xFFFF0000u);
    float la = a - fa;
    float lb = b - fb;
    asm("cvt.rn.bf16x2.f32 %0, %1, %2;" : "=r"(lo2) : "f"(lb), "f"(la));
}

/* ===== prepass: element-wise W -> bf16 hi/lo, full-occupancy grid ===== */
#define PRE_NB 1440
__global__ void __launch_bounds__(256)
prepass_kernel(const float* __restrict__ w) {
    const size_t idx = (size_t)blockIdx.x * 256 + threadIdx.x;
    const float4* __restrict__ w4 = (const float4*)w;
    float4 v = w4[idx];
    uint32_t h0, l0, h1, l1;
    cvt_split2(v.x, v.y, h0, l0);
    cvt_split2(v.z, v.w, h1, l1);
    ((uint2*)g_Wh)[idx] = make_uint2(h0, h1);
    ((uint2*)g_Wl)[idx] = make_uint2(l0, l1);
}

/* smem layout (bytes) */
#define SM_AH  0
#define SM_AL  12288
#define SM_BH  24576
#define SM_BL  36096
#define SM_TOT 47616

/* ===== GEMM: inline-x convert + triple-buffer cp.async B (native layout) ===== */
__global__ void __launch_bounds__(NTHR, 2)
gemm_kernel(const float* __restrict__ x) {
    __shared__ __align__(16) unsigned char sm[SM_TOT];

    const int tid  = threadIdx.x;
    const int warp = tid >> 5;
    const int ks   = blockIdx.x;
    const int nh   = blockIdx.y;
    const int mh   = blockIdx.z;
    const int kbase = ks * KPER;

    const float4* __restrict__ x4 = (const float4*)x;
    __nv_bfloat16* AhB = (__nv_bfloat16*)(sm + SM_AH);
    __nv_bfloat16* AlB = (__nv_bfloat16*)(sm + SM_AL);
    __nv_bfloat16* BhB = (__nv_bfloat16*)(sm + SM_BH);
    __nv_bfloat16* BlB = (__nv_bfloat16*)(sm + SM_BL);
    const uint32_t sb = smem_u32(sm);

    wmma::fragment<wmma::accumulator, 16, 16, 16, float> c[2][5];
    #pragma unroll
    for (int mt = 0; mt < 2; mt++)
        #pragma unroll
        for (int nt = 0; nt < 5; nt++) wmma::fill_fragment(c[mt][nt], 0.0f);

    float4 rx[4];

    auto load_x = [&](int s) {
        const int k0 = kbase + s * KT;
        #pragma unroll
        for (int j = 0; j < 4; j++) {
            int fid = j * NTHR + tid;
            int row = fid >> 2, xq = fid & 3;
            rx[j] = x4[(size_t)(mh * 128 + row) * K4 + (k0 >> 2) + xq];
        }
    };
    auto convert_x = [&](int d) {
        #pragma unroll
        for (int j = 0; j < 4; j++) {
            int fid = j * NTHR + tid;
            int row = fid >> 2, xq = fid & 3;
            uint32_t h0, l0, h1, l1;
            cvt_split2(rx[j].x, rx[j].y, h0, l0);
            cvt_split2(rx[j].z, rx[j].w, h1, l1);
            *(uint2*)(sm + SM_AH + d * 6144 + (row * LDA + xq * 4) * 2) = make_uint2(h0, h1);
            *(uint2*)(sm + SM_AL + d * 6144 + (row * LDA + xq * 4) * 2) = make_uint2(l0, l1);
        }
    };
    /* B tile stage s: rows (cl*16 + kk), 16 o's per row (32B = 2 cp16) */
    auto issue_b = [&](int s) {
        const int k0 = kbase + s * KT;
        const int d3 = s % 3;
        #pragma unroll
        for (int j = 0; j < 3; j++) {
            int u = j * NTHR + tid;
            if (u < 320) {
                int arr  = u >= 160;
                int rem  = u - arr * 160;
                int row  = rem >> 1;
                int half = u & 1;
                int cl   = row >> 4;
                int kk   = row & 15;
                const __nv_bfloat16* src =
                    (arr ? g_Wl : g_Wh)
                    + ((size_t)(nh * 5 + cl) * KDIM + k0 + kk) * OUT_CH + half * 8;
                uint32_t dst = sb + (arr ? SM_BL : SM_BH) + d3 * 3840
                             + (uint32_t)(row * LDA + half * 8) * 2;
                cp16(dst, src);
            }
        }
    };

    load_x(0);
    issue_b(0); cp_commit();
    issue_b(1); cp_commit();
    convert_x(0);
    load_x(1);
    __syncthreads();

    const int m0 = warp * 32;

    #pragma unroll
    for (int s = 0; s < NSTG; s++) {
        const int d  = s & 1;
        const int d3 = s % 3;
        if (s < NSTG - 1) cp_wait1(); else cp_wait0();
        __syncthreads();

        {
            wmma::fragment<wmma::matrix_a, 16, 16, 16, __nv_bfloat16, wmma::row_major> ah0, ah1, al0, al1;
            wmma::load_matrix_sync(ah0, AhB + d * 3072 + m0 * LDA, LDA);
            wmma::load_matrix_sync(ah1, AhB + d * 3072 + (m0 + 16) * LDA, LDA);
            wmma::load_matrix_sync(al0, AlB + d * 3072 + m0 * LDA, LDA);
            wmma::load_matrix_sync(al1, AlB + d * 3072 + (m0 + 16) * LDA, LDA);
            wmma::fragment<wmma::matrix_b, 16, 16, 16, __nv_bfloat16, wmma::row_major> bh[5], bl[5];
            #pragma unroll
            for (int nt = 0; nt < 5; nt++) {
                wmma::load_matrix_sync(bh[nt], BhB + d3 * 1920 + nt * 16 * LDA, LDA);
                wmma::load_matrix_sync(bl[nt], BlB + d3 * 1920 + nt * 16 * LDA, LDA);
            }
            #pragma unroll
            for (int nt = 0; nt < 5; nt++) {
                wmma::mma_sync(c[0][nt], ah0, bh[nt], c[0][nt]);
                wmma::mma_sync(c[1][nt], ah1, bh[nt], c[1][nt]);
            }
            #pragma unroll
            for (int nt = 0; nt < 5; nt++) {
                wmma::mma_sync(c[0][nt], ah0, bl[nt], c[0][nt]);
                wmma::mma_sync(c[1][nt], ah1, bl[nt], c[1][nt]);
            }
            #pragma unroll
            for (int nt = 0; nt < 5; nt++) {
                wmma::mma_sync(c[0][nt], al0, bh[nt], c[0][nt]);
                wmma::mma_sync(c[1][nt], al1, bh[nt], c[1][nt]);
            }
        }

        if (s + 1 < NSTG) {
            convert_x(d ^ 1);
            if (s + 2 < NSTG) {
                load_x(s + 2);
                issue_b(s + 2); cp_commit();
            }
        }
    }

    /* epilogue: partials [b][ks][n] */
    #pragma unroll
    for (int mt = 0; mt < 2; mt++)
        #pragma unroll
        for (int nt = 0; nt < 5; nt++)
            wmma::store_matrix_sync(
                g_Upart + (size_t)(mh * 128 + m0 + mt * 16) * PSTRIDE
                        + ks * NCOL + nh * 80 + nt * 16,
                c[mt][nt], PSTRIDE, wmma::mem_row_major);
}

/* ===== fused 72-way reduce (MLP-6 float4) + collapsed routing ===== */
__global__ void __launch_bounds__(512)
routing_kernel(float* __restrict__ out) {
    const int b = blockIdx.x;
    const int t = threadIdx.x;

    __shared__ __align__(16) float red[12][NCOL];
    __shared__ float L[NUM_C];

    if (t < 480) {
        const float4* src = (const float4*)(g_Upart + (size_t)b * PSTRIDE);
        float4 a0 = src[t];
        float4 a1 = src[t + 480];
        float4 a2 = src[t + 960];
        float4 a3 = src[t + 1440];
        float4 a4 = src[t + 1920];
        float4 a5 = src[t + 2400];
        float4 acc;
        acc.x = ((a0.x + a1.x) + (a2.x + a3.x)) + (a4.x + a5.x);
        acc.y = ((a0.y + a1.y) + (a2.y + a3.y)) + (a4.y + a5.y);
        acc.z = ((a0.z + a1.z) + (a2.z + a3.z)) + (a4.z + a5.z);
        acc.w = ((a0.w + a1.w) + (a2.w + a3.w)) + (a4.w + a5.w);
        *(float4*)&red[t / 40][(t % 40) * 4] = acc;
    }
    if (t < NUM_C) L[t] = 0.f;
    __syncthreads();

    const int cc = t >> 4;
    const int o  = t & 15;
    float u = 0.f, v = 0.f;
    if (t < NCOL) {
        float p0 = 0.f, p1 = 0.f, p2 = 0.f, p3 = 0.f;
        #pragma unroll
        for (int i = 0; i < 12; i += 4) {
            p0 += red[i][t];
            p1 += red[i + 1][t];
            p2 += red[i + 2][t];
            p3 += red[i + 3][t];
        }
        u = (p0 + p1) + (p2 + p3);
    }

    for (int it = 0; it < 3; it++) {
        float p = 0.f, S = 0.f;
        if (t < NCOL) {
            float mx = L[0];
            #pragma unroll
            for (int j = 1; j < NUM_C; j++) mx = fmaxf(mx, L[j]);
            float den = 0.f;
            #pragma unroll
            for (int j = 0; j < NUM_C; j++) den += __expf(L[j] - mx);
            p = __expf(L[cc] - mx) / den;

            float tv = p * u;
            v = tv * fabsf(tv) / (1.f + tv * tv);

            S = v;
            S += __shfl_xor_sync(0xffffffffu, S, 8);
            S += __shfl_xor_sync(0xffffffffu, S, 4);
            S += __shfl_xor_sync(0xffffffffu, S, 2);
            S += __shfl_xor_sync(0xffffffffu, S, 1);
        }
        __syncthreads();
        if (t < NCOL && o == 0) L[cc] += p * S;
        __syncthreads();
    }
    if (t < NCOL) out[(size_t)b * NCOL + t] = v;
}

extern "C" void kernel_launch(void* const* d_in, const int* in_sizes, int n_in,
                              void* d_out, int out_size) {
    const float* x = (const float*)d_in[0];
    const float* w = (const float*)d_in[1];
    if (n_in >= 2 && in_sizes[0] == NUM_C * KDIM * OUT_CH) {
        w = (const float*)d_in[0];
        x = (const float*)d_in[1];
    }
    prepass_kernel<<<PRE_NB, 256>>>(w);
    gemm_kernel<<<dim3(KSPLIT, 2, 2), NTHR>>>(x);
    routing_kernel<<<BATCH, 512>>>((float*)d_out);
    (void)out_size;
}

// round 17
// speedup vs baseline: 1.1090x; 1.1090x over previous
#include <cuda_runtime.h>
#include <cuda_bf16.h>
#include <mma.h>
#include <cstdint>
#include <math.h>

using namespace nvcuda;

#define NUM_C   10
#define OUT_CH  16
#define BATCH   256
#define KDIM    9216
#define K4      (KDIM / 4)
#define NCOL    160

#define KSPLIT  72
#define KPER    128            /* K per block */
#define KT      16             /* K per stage */
#define NSTG    8
#define NTHR    128            /* 4 warps */
#define LDA     24             /* padded bf16 row; 48B rows */
#define PSTRIDE (KSPLIT * NCOL)   /* 11520 */

/* partials: [b(256)][ks(72)][n(160)] — per-b contiguous for routing */
__device__ float g_Upart[BATCH * KSPLIT * NCOL];

__device__ __forceinline__ uint32_t smem_u32(const void* p) {
    uint32_t a;
    asm("{ .reg .u64 t; cvta.to.shared.u64 t, %1; cvt.u32.u64 %0, t; }"
        : "=r"(a) : "l"(p));
    return a;
}
__device__ __forceinline__ void cp16(uint32_t dst, const void* src) {
    asm volatile("cp.async.cg.shared.global [%0], [%1], 16;"
                 :: "r"(dst), "l"(src) : "memory");
}
__device__ __forceinline__ void cp_commit() {
    asm volatile("cp.async.commit_group;" ::: "memory");
}
__device__ __forceinline__ void cp_wait0() {
    asm volatile("cp.async.wait_group 0;" ::: "memory");
}
/* packed fp32 -> bf16 hi/lo split */
__device__ __forceinline__ void cvt_split2(float a, float b,
                                           uint32_t& hi2, uint32_t& lo2) {
    asm("cvt.rn.bf16x2.f32 %0, %1, %2;" : "=r"(hi2) : "f"(b), "f"(a));
    float fa = __uint_as_float(hi2 << 16);
    float fb = __uint_as_float(hi2 & 0xFFFF0000u);
    float la = a - fa;
    float lb = b - fb;
    asm("cvt.rn.bf16x2.f32 %0, %1, %2;" : "=r"(lo2) : "f"(lb), "f"(la));
}

/* ============ GEMM: pipelined 3-pass bf16-split wmma, split-K (R11 verbatim) ===== */
__global__ void __launch_bounds__(NTHR, 2)
gemm_kernel(const float* __restrict__ x, const float* __restrict__ w) {
    __shared__ __align__(16) __nv_bfloat16 Ah[2][128 * LDA];
    __shared__ __align__(16) __nv_bfloat16 Al[2][128 * LDA];
    __shared__ __align__(16) __nv_bfloat16 Bh[2][80 * LDA];
    __shared__ __align__(16) __nv_bfloat16 Bl[2][80 * LDA];

    const int tid  = threadIdx.x;
    const int warp = tid >> 5;
    const int ks   = blockIdx.x;
    const int nh   = blockIdx.y;
    const int mh   = blockIdx.z;
    const int kbase = ks * KPER;

    const float4* __restrict__ x4 = (const float4*)x;
    const float4* __restrict__ w4 = (const float4*)w;

    wmma::fragment<wmma::accumulator, 16, 16, 16, float> c[2][5];
    #pragma unroll
    for (int mt = 0; mt < 2; mt++)
        #pragma unroll
        for (int nt = 0; nt < 5; nt++) wmma::fill_fragment(c[mt][nt], 0.0f);

    float4 rx[4], rw[3];

    auto load_regs = [&](int k0) {
        #pragma unroll
        for (int j = 0; j < 4; j++) {
            int fid = j * NTHR + tid;
            int row = fid >> 2, xq = fid & 3;
            rx[j] = x4[(size_t)(mh * 128 + row) * K4 + (k0 >> 2) + xq];
        }
        #pragma unroll
        for (int j = 0; j < 3; j++) {
            if (j < 2 || tid < 64) {
                int fid = j * NTHR + tid;
                int cl = fid >> 6, rem = fid & 63;
                rw[j] = w4[((size_t)(nh * 5 + cl) * KDIM + k0 + (rem >> 2)) * 4 + (rem & 3)];
            }
        }
    };

    auto convert_store = [&](int d) {
        #pragma unroll
        for (int j = 0; j < 4; j++) {
            int fid = j * NTHR + tid;
            int row = fid >> 2, xq = fid & 3;
            uint32_t h0, l0, h1, l1;
            cvt_split2(rx[j].x, rx[j].y, h0, l0);
            cvt_split2(rx[j].z, rx[j].w, h1, l1);
            *(uint2*)&Ah[d][row * LDA + xq * 4] = make_uint2(h0, h1);
            *(uint2*)&Al[d][row * LDA + xq * 4] = make_uint2(l0, l1);
        }
        #pragma unroll
        for (int j = 0; j < 3; j++) {
            if (j < 2 || tid < 64) {
                int fid = j * NTHR + tid;
                int cl = fid >> 6, rem = fid & 63;
                int kloc = rem >> 2, o4 = rem & 3;
                int n0 = cl * 16 + o4 * 4;
                uint32_t hA, lA, hB, lB;
                cvt_split2(rw[j].x, rw[j].y, hA, lA);
                cvt_split2(rw[j].z, rw[j].w, hB, lB);
                uint16_t* bh = (uint16_t*)Bh[d];
                uint16_t* bl = (uint16_t*)Bl[d];
                bh[(n0 + 0) * LDA + kloc] = (uint16_t)(hA & 0xFFFFu);
                bh[(n0 + 1) * LDA + kloc] = (uint16_t)(hA >> 16);
                bh[(n0 + 2) * LDA + kloc] = (uint16_t)(hB & 0xFFFFu);
                bh[(n0 + 3) * LDA + kloc] = (uint16_t)(hB >> 16);
                bl[(n0 + 0) * LDA + kloc] = (uint16_t)(lA & 0xFFFFu);
                bl[(n0 + 1) * LDA + kloc] = (uint16_t)(lA >> 16);
                bl[(n0 + 2) * LDA + kloc] = (uint16_t)(lB & 0xFFFFu);
                bl[(n0 + 3) * LDA + kloc] = (uint16_t)(lB >> 16);
            }
        }
    };

    load_regs(kbase);
    convert_store(0);
    load_regs(kbase + KT);
    __syncthreads();

    const int m0 = warp * 32;

    #pragma unroll
    for (int s = 0; s < NSTG; s++) {
        const int d = s & 1;
        {
            wmma::fragment<wmma::matrix_a, 16, 16, 16, __nv_bfloat16, wmma::row_major> ah0, ah1, al0, al1;
            wmma::load_matrix_sync(ah0, &Ah[d][m0 * LDA], LDA);
            wmma::load_matrix_sync(ah1, &Ah[d][(m0 + 16) * LDA], LDA);
            wmma::load_matrix_sync(al0, &Al[d][m0 * LDA], LDA);
            wmma::load_matrix_sync(al1, &Al[d][(m0 + 16) * LDA], LDA);
            wmma::fragment<wmma::matrix_b, 16, 16, 16, __nv_bfloat16, wmma::col_major> bh[5], bl[5];
            #pragma unroll
            for (int nt = 0; nt < 5; nt++) {
                wmma::load_matrix_sync(bh[nt], &Bh[d][nt * 16 * LDA], LDA);
                wmma::load_matrix_sync(bl[nt], &Bl[d][nt * 16 * LDA], LDA);
            }
            #pragma unroll
            for (int nt = 0; nt < 5; nt++) {
                wmma::mma_sync(c[0][nt], ah0, bh[nt], c[0][nt]);
                wmma::mma_sync(c[1][nt], ah1, bh[nt], c[1][nt]);
            }
            #pragma unroll
            for (int nt = 0; nt < 5; nt++) {
                wmma::mma_sync(c[0][nt], ah0, bl[nt], c[0][nt]);
                wmma::mma_sync(c[1][nt], ah1, bl[nt], c[1][nt]);
            }
            #pragma unroll
            for (int nt = 0; nt < 5; nt++) {
                wmma::mma_sync(c[0][nt], al0, bh[nt], c[0][nt]);
                wmma::mma_sync(c[1][nt], al1, bh[nt], c[1][nt]);
            }
        }
        if (s + 1 < NSTG) {
            convert_store(d ^ 1);
            if (s + 2 < NSTG) load_regs(kbase + (s + 2) * KT);
        }
        __syncthreads();
    }

    /* epilogue: partials [b][ks][n] */
    #pragma unroll
    for (int mt = 0; mt < 2; mt++)
        #pragma unroll
        for (int nt = 0; nt < 5; nt++)
            wmma::store_matrix_sync(
                g_Upart + (size_t)(mh * 128 + m0 + mt * 16) * PSTRIDE
                        + ks * NCOL + nh * 80 + nt * 16,
                c[mt][nt], PSTRIDE, wmma::mem_row_major);
}

/* ===== routing v2: cp.async-stage full per-b span to smem, reduce, route ===== */
__global__ void __launch_bounds__(512)
routing_kernel(float* __restrict__ out) {
    const int b = blockIdx.x;
    const int t = threadIdx.x;

    __shared__ __align__(16) float buf[PSTRIDE];   /* 46080 B */
    __shared__ float L[NUM_C];

    /* stage 2880 float4 via cp.async (LSU-streamed, no register scoreboard) */
    {
        const float* src = g_Upart + (size_t)b * PSTRIDE;
        const uint32_t sdst = smem_u32(buf);
        #pragma unroll
        for (int j = 0; j < 6; j++) {
            int u = j * 512 + t;
            if (u < PSTRIDE / 4)
                cp16(sdst + (uint32_t)u * 16, src + u * 4);
        }
        cp_commit();
    }
    if (t < NUM_C) L[t] = 0.f;
    cp_wait0();
    __syncthreads();

    const int cc = t >> 4;
    const int o  = t & 15;
    float u = 0.f, v = 0.f;
    if (t < NCOL) {
        /* 72-way reduce from smem: lane n -> consecutive floats, conflict-free */
        float p0 = 0.f, p1 = 0.f, p2 = 0.f, p3 = 0.f;
        #pragma unroll
        for (int ksl = 0; ksl < KSPLIT; ksl += 4) {
            p0 += buf[(ksl + 0) * NCOL + t];
            p1 += buf[(ksl + 1) * NCOL + t];
            p2 += buf[(ksl + 2) * NCOL + t];
            p3 += buf[(ksl + 3) * NCOL + t];
        }
        u = (p0 + p1) + (p2 + p3);
    }

    for (int it = 0; it < 3; it++) {
        float p = 0.f, S = 0.f;
        if (t < NCOL) {
            float mx = L[0];
            #pragma unroll
            for (int j = 1; j < NUM_C; j++) mx = fmaxf(mx, L[j]);
            float den = 0.f;
            #pragma unroll
            for (int j = 0; j < NUM_C; j++) den += __expf(L[j] - mx);
            p = __expf(L[cc] - mx) / den;

            float tv = p * u;
            v = tv * fabsf(tv) / (1.f + tv * tv);

            S = v;
            S += __shfl_xor_sync(0xffffffffu, S, 8);
            S += __shfl_xor_sync(0xffffffffu, S, 4);
            S += __shfl_xor_sync(0xffffffffu, S, 2);
            S += __shfl_xor_sync(0xffffffffu, S, 1);
        }
        __syncthreads();
        if (t < NCOL && o == 0) L[cc] += p * S;
        __syncthreads();
    }
    if (t < NCOL) out[(size_t)b * NCOL + t] = v;
}

extern "C" void kernel_launch(void* const* d_in, const int* in_sizes, int n_in,
                              void* d_out, int out_size) {
    const float* x = (const float*)d_in[0];
    const float* w = (const float*)d_in[1];
    if (n_in >= 2 && in_sizes[0] == NUM_C * KDIM * OUT_CH) {
        w = (const float*)d_in[0];
        x = (const float*)d_in[1];
    }
    gemm_kernel<<<dim3(KSPLIT, 2, 2), NTHR>>>(x, w);
    routing_kernel<<<BATCH, 512>>>((float*)d_out);
    (void)out_size;
}